// round 16
// baseline (speedup 1.0000x reference)
#include <cuda_runtime.h>

#define HWSZ 3136          // 56*56
#define NPOS 25088         // B*H*W
#define WS_STRIDE 196      // qkv padded weight-smem row stride (floats)
#define PSTR 64            // attn smem per-position stride (floats)
#define HALOW 12           // 12x12 halo for 8x8 tile
#define HALON 144

// ---------------- scratch (no cudaMalloc allowed) ----------------
__device__ float g_qkv[(size_t)NPOS * 192];   // [pos][q(64)|k(64)|v(64)]
__device__ float g_wfold[1728];               // [3][9][64] folded conv weights (pre-scaled by rate2)

__device__ __forceinline__ int refl(int i) {
    return i < 0 ? -i : (i >= 56 ? 110 - i : i);
}
// packed f32x2 helpers (Blackwell; ptxas never emits these from C++)
typedef unsigned long long ull;
__device__ __forceinline__ ull bc2(float x) {
    ull r; asm("mov.b64 %0,{%1,%1};" : "=l"(r) : "f"(x)); return r;
}
__device__ __forceinline__ ull pk2(float lo, float hi) {
    ull r; asm("mov.b64 %0,{%1,%2};" : "=l"(r) : "f"(lo), "f"(hi)); return r;
}
__device__ __forceinline__ void fma2(ull& d, ull a, ull b) {
    asm("fma.rn.f32x2 %0,%1,%2,%0;" : "+l"(d) : "l"(a), "l"(b));
}
__device__ __forceinline__ float2 up2(ull v) {
    float2 r; asm("mov.b64 {%0,%1},%2;" : "=f"(r.x), "=f"(r.y) : "l"(v)); return r;
}
// 8-lane segment reductions via shfl butterfly (redux.sync.f32 absent on sm_100)
__device__ __forceinline__ float seg8_add(float v) {
    v += __shfl_xor_sync(0xffffffffu, v, 1);
    v += __shfl_xor_sync(0xffffffffu, v, 2);
    v += __shfl_xor_sync(0xffffffffu, v, 4);
    return v;
}
__device__ __forceinline__ float seg8_max(float v) {
    v = fmaxf(v, __shfl_xor_sync(0xffffffffu, v, 1));
    v = fmaxf(v, __shfl_xor_sync(0xffffffffu, v, 2));
    v = fmaxf(v, __shfl_xor_sync(0xffffffffu, v, 4));
    return v;
}

// ---------------- kernel 1: q,k,v 1x1 convs (GEMM, f32x2 packed) ----------------
// x loads software-pipelined with a depth-4 register ring (MLP ~4-5).
__global__ __launch_bounds__(256, 3) void qkv_kernel(
    const float* __restrict__ x,
    const float* __restrict__ w1, const float* __restrict__ b1,
    const float* __restrict__ w2, const float* __restrict__ b2,
    const float* __restrict__ w3, const float* __restrict__ b3,
    const float* __restrict__ w_fc, const float* __restrict__ w_dep,
    const float* __restrict__ rate2) {
    extern __shared__ float sm[];
    float* ws = sm;                          // [64 cin][WS_STRIDE] holding 192 oc
    float* bs = sm + 64 * WS_STRIDE;         // [192]

    const int b = blockIdx.y;
    const int pos0 = blockIdx.x * 64;        // 49 tiles * 64 = 3136 exact
    const int tid = threadIdx.x;

    // block (0,0) folds the depthwise-conv weights (pre-scaled by rate2):
    // g_wfold[c][t][d] = rate2 * sum_m w_dep[d][m][t] * w_fc[m][c]
    if (blockIdx.x == 0 && blockIdx.y == 0) {
        const float r2 = rate2[0];
        for (int i = tid; i < 1728; i += 256) {
            int c = i / 576, r = i % 576, t = r >> 6, d = r & 63;
            float s = 0.f;
#pragma unroll
            for (int m = 0; m < 9; ++m)
                s += w_dep[(d * 9 + m) * 9 + t] * w_fc[m * 3 + c];
            g_wfold[i] = s * r2;
        }
    }

    for (int i = tid; i < 4096; i += 256) {
        int oc = i >> 6, cin = i & 63;
        ws[cin * WS_STRIDE + oc] = w1[i];
        ws[cin * WS_STRIDE + 64 + oc] = w2[i];
        ws[cin * WS_STRIDE + 128 + oc] = w3[i];
    }
    if (tid < 192)
        bs[tid] = (tid < 64) ? b1[tid] : (tid < 128 ? b2[tid - 64] : b3[tid - 128]);
    __syncthreads();

    const int w = tid >> 5;    // warp 0..7 -> 8 positions
    const int og = tid & 31;   // lane -> 6 output chans

    ull acc[4][6];             // [pos-pair][oc]
#pragma unroll
    for (int p = 0; p < 4; ++p)
#pragma unroll
        for (int j = 0; j < 6; ++j) acc[p][j] = 0ull;

    const float* xw = x + (size_t)b * 64 * HWSZ + pos0 + w * 8;

    // depth-4 prefetch ring on x
    float4 bufa[4], bufb[4];
#pragma unroll
    for (int j = 0; j < 4; ++j) {
        bufa[j] = __ldg((const float4*)(xw + (size_t)j * HWSZ));
        bufb[j] = __ldg((const float4*)(xw + (size_t)j * HWSZ + 4));
    }

#pragma unroll 4
    for (int cin = 0; cin < 64; ++cin) {
        float4 xa = bufa[cin & 3];
        float4 xb = bufb[cin & 3];
        if (cin + 4 < 64) {
            bufa[cin & 3] = __ldg((const float4*)(xw + (size_t)(cin + 4) * HWSZ));
            bufb[cin & 3] = __ldg((const float4*)(xw + (size_t)(cin + 4) * HWSZ + 4));
        }
        ull xp[4] = {pk2(xa.x, xa.y), pk2(xa.z, xa.w),
                     pk2(xb.x, xb.y), pk2(xb.z, xb.w)};
        const float2* wr = (const float2*)(ws + cin * WS_STRIDE + og * 6);
        float2 wa = wr[0], wb = wr[1], wc = wr[2];
        ull bw[6] = {bc2(wa.x), bc2(wa.y), bc2(wb.x),
                     bc2(wb.y), bc2(wc.x), bc2(wc.y)};
#pragma unroll
        for (int p = 0; p < 4; ++p) {
            fma2(acc[p][0], xp[p], bw[0]);
            fma2(acc[p][1], xp[p], bw[1]);
            fma2(acc[p][2], xp[p], bw[2]);
            fma2(acc[p][3], xp[p], bw[3]);
            fma2(acc[p][4], xp[p], bw[4]);
            fma2(acc[p][5], xp[p], bw[5]);
        }
    }

    float bl[6];
#pragma unroll
    for (int j = 0; j < 6; ++j) bl[j] = bs[og * 6 + j];

#pragma unroll
    for (int p = 0; p < 4; ++p) {
        float2 v[6];
#pragma unroll
        for (int j = 0; j < 6; ++j) v[j] = up2(acc[p][j]);
        float* dlo = g_qkv + ((size_t)(b * HWSZ + pos0 + w * 8 + 2 * p)) * 192 + og * 6;
        float2 l0 = {v[0].x + bl[0], v[1].x + bl[1]};
        float2 l1 = {v[2].x + bl[2], v[3].x + bl[3]};
        float2 l2 = {v[4].x + bl[4], v[5].x + bl[5]};
        *(float2*)(dlo + 0) = l0; *(float2*)(dlo + 2) = l1; *(float2*)(dlo + 4) = l2;
        float* dhi = dlo + 192;
        float2 h0 = {v[0].y + bl[0], v[1].y + bl[1]};
        float2 h1 = {v[2].y + bl[2], v[3].y + bl[3]};
        float2 h2 = {v[4].y + bl[4], v[5].y + bl[5]};
        *(float2*)(dhi + 0) = h0; *(float2*)(dhi + 2) = h1; *(float2*)(dhi + 4) = h2;
    }
}

// ---------------- kernel 2: fused attention + conv branch (unchanged R15) ----------------
__global__ __launch_bounds__(256, 3) void attn_kernel(
    const float* __restrict__ wp,
    const float* __restrict__ b_dep,
    const float* __restrict__ rate1,
    const float* __restrict__ rate2,
    float* __restrict__ out) {
    extern __shared__ float sm[];
    float* ks = sm;                      // [HALON][PSTR]
    float* vs = sm + HALON * PSTR;

    const int b = blockIdx.z;
    const int ty0 = blockIdx.y * 8;
    const int tx0 = blockIdx.x * 8;
    const int tid = threadIdx.x;
    const float* wfold = g_wfold;

    // halo load: 144 positions x k,v 128 channels, reflect-padded, f4 coalesced
    for (int i = tid; i < HALON * 32; i += 256) {
        int hpos = i >> 5;
        int c4 = 16 + (i & 31);
        int hy = hpos / HALOW, hx = hpos % HALOW;
        int gy = refl(ty0 + hy - 2);
        int gx = refl(tx0 + hx - 2);
        float4 v = *(const float4*)(g_qkv +
            ((size_t)(b * HWSZ + gy * 56 + gx)) * 192 + c4 * 4);
        float* arr = (c4 < 32) ? ks : vs;
        *(float4*)(arr + hpos * PSTR + (c4 & 15) * 4) = v;
    }
    __syncthreads();

    const int pp = tid >> 3;            // pair 0..31
    const int s = tid & 7;              // channel sub / tap owner
    const int py = pp >> 2;             // 0..7
    const int px0 = (pp & 3) * 2;       // 0,2,4,6
    const int gy = ty0 + py, gx0 = tx0 + px0, gx1 = gx0 + 1;
    const int chidx = (py + 2) * HALOW + (px0 + 2);
    const int sb = s * 4;

    // q for both positions from gmem (L1-resident), packed pairs
    const float* qg0 = g_qkv + ((size_t)(b * HWSZ + gy * 56 + gx0)) * 192 + sb;
    ull qp0[4], qp1[4];
    float qr0[8], qr1[8];
    {
        float4 v0 = *(const float4*)(qg0);
        float4 v1 = *(const float4*)(qg0 + 32);
        qr0[0] = v0.x; qr0[1] = v0.y; qr0[2] = v0.z; qr0[3] = v0.w;
        qr0[4] = v1.x; qr0[5] = v1.y; qr0[6] = v1.z; qr0[7] = v1.w;
        qp0[0] = pk2(v0.x, v0.y); qp0[1] = pk2(v0.z, v0.w);
        qp0[2] = pk2(v1.x, v1.y); qp0[3] = pk2(v1.z, v1.w);
        float4 u0 = *(const float4*)(qg0 + 192);
        float4 u1 = *(const float4*)(qg0 + 224);
        qr1[0] = u0.x; qr1[1] = u0.y; qr1[2] = u0.z; qr1[3] = u0.w;
        qr1[4] = u1.x; qr1[5] = u1.y; qr1[6] = u1.z; qr1[7] = u1.w;
        qp1[0] = pk2(u0.x, u0.y); qp1[1] = pk2(u0.z, u0.w);
        qp1[2] = pk2(u1.x, u1.y); qp1[3] = pk2(u1.z, u1.w);
    }

    // packed conv accumulators (rate2 folded into weights)
    ull ocv0[4], ocv1[4];
#pragma unroll
    for (int c = 0; c < 4; ++c) { ocv0[c] = 0ull; ocv1[c] = 0ull; }

    // q-conv: 12 shared data loads serve 9+9 taps (zero padding via predicate)
#pragma unroll
    for (int dy = -1; dy <= 1; ++dy)
#pragma unroll
        for (int dx = -1; dx <= 2; ++dx) {
            if ((unsigned)(gy + dy) < 56u && (unsigned)(gx0 + dx) < 56u) {
                const float* qp = qg0 + (dy * 56 + dx) * 192;
                float4 q0 = *(const float4*)(qp);
                float4 q1 = *(const float4*)(qp + 32);
                ull qpk[4] = {pk2(q0.x, q0.y), pk2(q0.z, q0.w),
                              pk2(q1.x, q1.y), pk2(q1.z, q1.w)};
                if (dx <= 1) {
                    const float* wq = wfold + ((dy + 1) * 3 + dx + 1) * 64 + sb;
                    float4 w0 = __ldg((const float4*)(wq));
                    float4 w1 = __ldg((const float4*)(wq + 32));
                    fma2(ocv0[0], qpk[0], pk2(w0.x, w0.y));
                    fma2(ocv0[1], qpk[1], pk2(w0.z, w0.w));
                    fma2(ocv0[2], qpk[2], pk2(w1.x, w1.y));
                    fma2(ocv0[3], qpk[3], pk2(w1.z, w1.w));
                }
                if (dx >= 0) {
                    const float* wq = wfold + ((dy + 1) * 3 + dx) * 64 + sb;
                    float4 w0 = __ldg((const float4*)(wq));
                    float4 w1 = __ldg((const float4*)(wq + 32));
                    fma2(ocv1[0], qpk[0], pk2(w0.x, w0.y));
                    fma2(ocv1[1], qpk[1], pk2(w0.z, w0.w));
                    fma2(ocv1[2], qpk[2], pk2(w1.x, w1.y));
                    fma2(ocv1[3], qpk[3], pk2(w1.z, w1.w));
                }
            }
        }

    // phase 1: 30 k loads -> 50 packed dots (25 per position) + fused k-conv
    float attp0[4] = {0.f, 0.f, 0.f, 0.f};
    float attp1[4] = {0.f, 0.f, 0.f, 0.f};
#pragma unroll
    for (int dy = -2; dy <= 2; ++dy)
#pragma unroll
        for (int dx = -2; dx <= 3; ++dx) {
            const float* kb = ks + (chidx + dy * HALOW + dx) * PSTR + sb;
            float4 k0 = *(const float4*)(kb);
            float4 k1 = *(const float4*)(kb + 32);
            ull kpk[4] = {pk2(k0.x, k0.y), pk2(k0.z, k0.w),
                          pk2(k1.x, k1.y), pk2(k1.z, k1.w)};
            // fused k-conv (inner taps, zero padding)
            if (dy >= -1 && dy <= 1) {
                if ((unsigned)(gy + dy) < 56u && (unsigned)(gx0 + dx) < 56u) {
                    if (dx >= -1 && dx <= 1) {
                        const float* wk = wfold + 576 + ((dy + 1) * 3 + dx + 1) * 64 + sb;
                        float4 w0 = __ldg((const float4*)(wk));
                        float4 w1 = __ldg((const float4*)(wk + 32));
                        fma2(ocv0[0], kpk[0], pk2(w0.x, w0.y));
                        fma2(ocv0[1], kpk[1], pk2(w0.z, w0.w));
                        fma2(ocv0[2], kpk[2], pk2(w1.x, w1.y));
                        fma2(ocv0[3], kpk[3], pk2(w1.z, w1.w));
                    }
                    if (dx >= 0 && dx <= 2) {
                        const float* wk = wfold + 576 + ((dy + 1) * 3 + dx) * 64 + sb;
                        float4 w0 = __ldg((const float4*)(wk));
                        float4 w1 = __ldg((const float4*)(wk + 32));
                        fma2(ocv1[0], kpk[0], pk2(w0.x, w0.y));
                        fma2(ocv1[1], kpk[1], pk2(w0.z, w0.w));
                        fma2(ocv1[2], kpk[2], pk2(w1.x, w1.y));
                        fma2(ocv1[3], kpk[3], pk2(w1.z, w1.w));
                    }
                }
            }
            if (dx <= 2) {   // tap (dy,dx) of pos0, packed dot
                ull da = 0ull;
                fma2(da, qp0[0], kpk[0]);
                fma2(da, qp0[1], kpk[1]);
                fma2(da, qp0[2], kpk[2]);
                fma2(da, qp0[3], kpk[3]);
                float2 dd = up2(da);
                float d = seg8_add(dd.x + dd.y);
                const int j = (dy + 2) * 5 + dx + 2;
                if ((j & 7) == s) attp0[j >> 3] = d;
            }
            if (dx >= -1) {  // tap (dy,dx-1) of pos1, packed dot
                ull da = 0ull;
                fma2(da, qp1[0], kpk[0]);
                fma2(da, qp1[1], kpk[1]);
                fma2(da, qp1[2], kpk[2]);
                fma2(da, qp1[3], kpk[3]);
                float2 dd = up2(da);
                float d = seg8_add(dd.x + dd.y);
                const int j = (dy + 2) * 5 + dx + 1;
                if ((j & 7) == s) attp1[j >> 3] = d;
            }
        }

    // PE dots per position (bp cancels analytically)
    float a0 = 0.f, bq0 = 0.f, a1 = 0.f, bq1 = 0.f;
#pragma unroll
    for (int i = 0; i < 2; ++i)
#pragma unroll
        for (int j = 0; j < 4; ++j) {
            int ch = i * 32 + s * 4 + j;
            float2 w = __ldg((const float2*)wp + ch);
            a0 += qr0[i * 4 + j] * w.x; bq0 += qr0[i * 4 + j] * w.y;
            a1 += qr1[i * 4 + j] * w.x; bq1 += qr1[i * 4 + j] * w.y;
        }
    a0 = seg8_add(a0);
    bq0 = seg8_add(bq0);
    a1 = seg8_add(a1);
    bq1 = seg8_add(bq1);

    // phase 2: distributed softmax (lane s owns taps j%8==s), per position
    const float scaling = 0.125f;        // 64^-0.5
    const float lstep = 2.f / 55.f;
    const float r1 = rate1[0];
    const float r2 = rate2[0];

    float mx0 = -1e30f, mx1 = -1e30f;
#pragma unroll
    for (int i = 0; i < 4; ++i) {
        int j = s + 8 * i;
        if (j < 25) {
            int dy = j / 5 - 2, dx = j % 5 - 2;
            int gyj = refl(gy + dy);
            float t0 = scaling * (attp0[i] + a0 * ((float)(gx0 - refl(gx0 + dx)) * lstep) +
                                  bq0 * ((float)(gy - gyj) * lstep));
            float t1 = scaling * (attp1[i] + a1 * ((float)(gx1 - refl(gx1 + dx)) * lstep) +
                                  bq1 * ((float)(gy - gyj) * lstep));
            attp0[i] = t0; mx0 = fmaxf(mx0, t0);
            attp1[i] = t1; mx1 = fmaxf(mx1, t1);
        } else {
            attp0[i] = -1e30f;
            attp1[i] = -1e30f;
        }
    }
    mx0 = seg8_max(mx0);
    mx1 = seg8_max(mx1);
    float ss0 = 0.f, ss1 = 0.f;
#pragma unroll
    for (int i = 0; i < 4; ++i) {
        float e0 = __expf(attp0[i] - mx0); attp0[i] = e0; ss0 += e0;
        float e1 = __expf(attp1[i] - mx1); attp1[i] = e1; ss1 += e1;
    }
    ss0 = seg8_add(ss0);
    ss1 = seg8_add(ss1);
    const float c0n = r1 / ss0, c1n = r1 / ss1;
#pragma unroll
    for (int i = 0; i < 4; ++i) { attp0[i] *= c0n; attp1[i] *= c1n; }

    // phase 3: 30 v loads -> packed attention accumulate + fused v-conv
    ull oav0[4], oav1[4];
#pragma unroll
    for (int c = 0; c < 4; ++c) { oav0[c] = 0ull; oav1[c] = 0ull; }
#pragma unroll
    for (int dy = -2; dy <= 2; ++dy)
#pragma unroll
        for (int dx = -2; dx <= 3; ++dx) {
            const float* vb = vs + (chidx + dy * HALOW + dx) * PSTR + sb;
            float4 v0 = *(const float4*)(vb);
            float4 v1 = *(const float4*)(vb + 32);
            ull vpk[4] = {pk2(v0.x, v0.y), pk2(v0.z, v0.w),
                          pk2(v1.x, v1.y), pk2(v1.z, v1.w)};
            if (dx <= 2) {
                const int j = (dy + 2) * 5 + dx + 2;
                const float w = __shfl_sync(0xffffffffu, attp0[j >> 3], j & 7, 8);
                ull wb = bc2(w);
                fma2(oav0[0], vpk[0], wb);
                fma2(oav0[1], vpk[1], wb);
                fma2(oav0[2], vpk[2], wb);
                fma2(oav0[3], vpk[3], wb);
            }
            if (dx >= -1) {
                const int j = (dy + 2) * 5 + dx + 1;
                const float w = __shfl_sync(0xffffffffu, attp1[j >> 3], j & 7, 8);
                ull wb = bc2(w);
                fma2(oav1[0], vpk[0], wb);
                fma2(oav1[1], vpk[1], wb);
                fma2(oav1[2], vpk[2], wb);
                fma2(oav1[3], vpk[3], wb);
            }
            if (dy >= -1 && dy <= 1) {   // fused v-conv, zero padding
                if ((unsigned)(gy + dy) < 56u && (unsigned)(gx0 + dx) < 56u) {
                    if (dx >= -1 && dx <= 1) {
                        const float* wv = wfold + 1152 + ((dy + 1) * 3 + dx + 1) * 64 + sb;
                        float4 w0 = __ldg((const float4*)(wv));
                        float4 w1 = __ldg((const float4*)(wv + 32));
                        fma2(ocv0[0], vpk[0], pk2(w0.x, w0.y));
                        fma2(ocv0[1], vpk[1], pk2(w0.z, w0.w));
                        fma2(ocv0[2], vpk[2], pk2(w1.x, w1.y));
                        fma2(ocv0[3], vpk[3], pk2(w1.z, w1.w));
                    }
                    if (dx >= 0 && dx <= 2) {
                        const float* wv = wfold + 1152 + ((dy + 1) * 3 + dx) * 64 + sb;
                        float4 w0 = __ldg((const float4*)(wv));
                        float4 w1 = __ldg((const float4*)(wv + 32));
                        fma2(ocv1[0], vpk[0], pk2(w0.x, w0.y));
                        fma2(ocv1[1], vpk[1], pk2(w0.z, w0.w));
                        fma2(ocv1[2], vpk[2], pk2(w1.x, w1.y));
                        fma2(ocv1[3], vpk[3], pk2(w1.z, w1.w));
                    }
                }
            }
        }

#pragma unroll
    for (int c = 0; c < 4; ++c) {
        float2 av0 = up2(oav0[c]), av1 = up2(oav1[c]);
        float2 cv0 = up2(ocv0[c]), cv1 = up2(ocv1[c]);
        // pair c covers channels: i = c>>1, base = i*32 + s*4 + (c&1)*2
        int ch0 = (c >> 1) * 32 + s * 4 + (c & 1) * 2;
#pragma unroll
        for (int h = 0; h < 2; ++h) {
            int ch = ch0 + h;
            float bd = __ldg(b_dep + ch);
            float2 res;
            res.x = (h ? av0.y : av0.x) + (h ? cv0.y : cv0.x) + r2 * bd;
            res.y = (h ? av1.y : av1.x) + (h ? cv1.y : cv1.x) + r2 * bd;
            *(float2*)(out + ((size_t)(b * 64 + ch) * 56 + gy) * 56 + gx0) = res;
        }
    }
}

// ---------------- launch ----------------
extern "C" void kernel_launch(void* const* d_in, const int* in_sizes, int n_in,
                              void* d_out, int out_size) {
    const float* x    = (const float*)d_in[0];
    const float* w1   = (const float*)d_in[1];
    const float* b1   = (const float*)d_in[2];
    const float* w2   = (const float*)d_in[3];
    const float* b2   = (const float*)d_in[4];
    const float* w3   = (const float*)d_in[5];
    const float* b3   = (const float*)d_in[6];
    const float* wp   = (const float*)d_in[7];
    // d_in[8] = bp (cancels analytically)
    const float* w_fc = (const float*)d_in[9];
    const float* w_dep = (const float*)d_in[10];
    const float* b_dep = (const float*)d_in[11];
    const float* rate1 = (const float*)d_in[12];
    const float* rate2 = (const float*)d_in[13];
    float* out = (float*)d_out;

    const int qkv_smem = (64 * WS_STRIDE + 192) * 4;
    const int att_smem = 2 * HALON * PSTR * 4;   // 73728 B (k+v)
    cudaFuncSetAttribute(qkv_kernel, cudaFuncAttributeMaxDynamicSharedMemorySize, qkv_smem);
    cudaFuncSetAttribute(attn_kernel, cudaFuncAttributeMaxDynamicSharedMemorySize, att_smem);

    qkv_kernel<<<dim3(49, 8), 256, qkv_smem>>>(x, w1, b1, w2, b2, w3, b3, w_fc, w_dep, rate2);
    attn_kernel<<<dim3(7, 7, 8), 256, att_smem>>>(wp, b_dep, rate1, rate2, out);
}

// round 17
// speedup vs baseline: 2.1487x; 2.1487x over previous
#include <cuda_runtime.h>

#define HWSZ 3136          // 56*56
#define NPOS 25088         // B*H*W
#define WS_STRIDE 196      // qkv padded weight-smem row stride (floats)
#define PSTR 64            // attn smem per-position stride (floats)
#define HALOW 12           // 12x12 halo for 8x8 tile
#define HALON 144

// ---------------- scratch (no cudaMalloc allowed) ----------------
__device__ float g_qkv[(size_t)NPOS * 192];   // [pos][q(64)|k(64)|v(64)]
__device__ float g_wfold[1728];               // [3][9][64] folded conv weights (pre-scaled by rate2)

__device__ __forceinline__ int refl(int i) {
    return i < 0 ? -i : (i >= 56 ? 110 - i : i);
}
// packed f32x2 helpers (Blackwell; ptxas never emits these from C++)
typedef unsigned long long ull;
__device__ __forceinline__ ull bc2(float x) {
    ull r; asm("mov.b64 %0,{%1,%1};" : "=l"(r) : "f"(x)); return r;
}
__device__ __forceinline__ ull pk2(float lo, float hi) {
    ull r; asm("mov.b64 %0,{%1,%2};" : "=l"(r) : "f"(lo), "f"(hi)); return r;
}
__device__ __forceinline__ void fma2(ull& d, ull a, ull b) {
    asm("fma.rn.f32x2 %0,%1,%2,%0;" : "+l"(d) : "l"(a), "l"(b));
}
__device__ __forceinline__ float2 up2(ull v) {
    float2 r; asm("mov.b64 {%0,%1},%2;" : "=f"(r.x), "=f"(r.y) : "l"(v)); return r;
}
// 8-lane segment reductions via shfl butterfly (redux.sync.f32 absent on sm_100)
__device__ __forceinline__ float seg8_add(float v) {
    v += __shfl_xor_sync(0xffffffffu, v, 1);
    v += __shfl_xor_sync(0xffffffffu, v, 2);
    v += __shfl_xor_sync(0xffffffffu, v, 4);
    return v;
}
__device__ __forceinline__ float seg8_max(float v) {
    v = fmaxf(v, __shfl_xor_sync(0xffffffffu, v, 1));
    v = fmaxf(v, __shfl_xor_sync(0xffffffffu, v, 2));
    v = fmaxf(v, __shfl_xor_sync(0xffffffffu, v, 4));
    return v;
}

// ---------------- kernel 1: q,k,v 1x1 convs (GEMM, f32x2 packed) ----------------
// Loads kept inside the loop; unroll-4 lets ptxas front-batch 4 iterations'
// LDG.128s (MLP~4) without cross-iteration live ranges (no spill risk).
__global__ __launch_bounds__(256, 3) void qkv_kernel(
    const float* __restrict__ x,
    const float* __restrict__ w1, const float* __restrict__ b1,
    const float* __restrict__ w2, const float* __restrict__ b2,
    const float* __restrict__ w3, const float* __restrict__ b3,
    const float* __restrict__ w_fc, const float* __restrict__ w_dep,
    const float* __restrict__ rate2) {
    extern __shared__ float sm[];
    float* ws = sm;                          // [64 cin][WS_STRIDE] holding 192 oc
    float* bs = sm + 64 * WS_STRIDE;         // [192]

    const int b = blockIdx.y;
    const int pos0 = blockIdx.x * 64;        // 49 tiles * 64 = 3136 exact
    const int tid = threadIdx.x;

    // block (0,0) folds the depthwise-conv weights (pre-scaled by rate2):
    // g_wfold[c][t][d] = rate2 * sum_m w_dep[d][m][t] * w_fc[m][c]
    if (blockIdx.x == 0 && blockIdx.y == 0) {
        const float r2 = rate2[0];
        for (int i = tid; i < 1728; i += 256) {
            int c = i / 576, r = i % 576, t = r >> 6, d = r & 63;
            float s = 0.f;
#pragma unroll
            for (int m = 0; m < 9; ++m)
                s += w_dep[(d * 9 + m) * 9 + t] * w_fc[m * 3 + c];
            g_wfold[i] = s * r2;
        }
    }

    for (int i = tid; i < 4096; i += 256) {
        int oc = i >> 6, cin = i & 63;
        ws[cin * WS_STRIDE + oc] = w1[i];
        ws[cin * WS_STRIDE + 64 + oc] = w2[i];
        ws[cin * WS_STRIDE + 128 + oc] = w3[i];
    }
    if (tid < 192)
        bs[tid] = (tid < 64) ? b1[tid] : (tid < 128 ? b2[tid - 64] : b3[tid - 128]);
    __syncthreads();

    const int w = tid >> 5;    // warp 0..7 -> 8 positions
    const int og = tid & 31;   // lane -> 6 output chans

    ull acc[4][6];             // [pos-pair][oc]
#pragma unroll
    for (int p = 0; p < 4; ++p)
#pragma unroll
        for (int j = 0; j < 6; ++j) acc[p][j] = 0ull;

    const float* xw = x + (size_t)b * 64 * HWSZ + pos0 + w * 8;
#pragma unroll 4
    for (int cin = 0; cin < 64; ++cin) {
        float4 xa = __ldg((const float4*)(xw + (size_t)cin * HWSZ));      // pos 8w..+3
        float4 xb = __ldg((const float4*)(xw + (size_t)cin * HWSZ + 4));  // pos 8w+4..+7
        ull xp[4] = {pk2(xa.x, xa.y), pk2(xa.z, xa.w),
                     pk2(xb.x, xb.y), pk2(xb.z, xb.w)};
        const float2* wr = (const float2*)(ws + cin * WS_STRIDE + og * 6);
        float2 wa = wr[0], wb = wr[1], wc = wr[2];
        ull bw[6] = {bc2(wa.x), bc2(wa.y), bc2(wb.x),
                     bc2(wb.y), bc2(wc.x), bc2(wc.y)};
#pragma unroll
        for (int p = 0; p < 4; ++p) {
            fma2(acc[p][0], xp[p], bw[0]);
            fma2(acc[p][1], xp[p], bw[1]);
            fma2(acc[p][2], xp[p], bw[2]);
            fma2(acc[p][3], xp[p], bw[3]);
            fma2(acc[p][4], xp[p], bw[4]);
            fma2(acc[p][5], xp[p], bw[5]);
        }
    }

    float bl[6];
#pragma unroll
    for (int j = 0; j < 6; ++j) bl[j] = bs[og * 6 + j];

#pragma unroll
    for (int p = 0; p < 4; ++p) {
        float2 v[6];
#pragma unroll
        for (int j = 0; j < 6; ++j) v[j] = up2(acc[p][j]);
        float* dlo = g_qkv + ((size_t)(b * HWSZ + pos0 + w * 8 + 2 * p)) * 192 + og * 6;
        float2 l0 = {v[0].x + bl[0], v[1].x + bl[1]};
        float2 l1 = {v[2].x + bl[2], v[3].x + bl[3]};
        float2 l2 = {v[4].x + bl[4], v[5].x + bl[5]};
        *(float2*)(dlo + 0) = l0; *(float2*)(dlo + 2) = l1; *(float2*)(dlo + 4) = l2;
        float* dhi = dlo + 192;
        float2 h0 = {v[0].y + bl[0], v[1].y + bl[1]};
        float2 h1 = {v[2].y + bl[2], v[3].y + bl[3]};
        float2 h2 = {v[4].y + bl[4], v[5].y + bl[5]};
        *(float2*)(dhi + 0) = h0; *(float2*)(dhi + 2) = h1; *(float2*)(dhi + 4) = h2;
    }
}

// ---------------- kernel 2: fused attention + conv branch (unchanged) ----------------
__global__ __launch_bounds__(256, 3) void attn_kernel(
    const float* __restrict__ wp,
    const float* __restrict__ b_dep,
    const float* __restrict__ rate1,
    const float* __restrict__ rate2,
    float* __restrict__ out) {
    extern __shared__ float sm[];
    float* ks = sm;                      // [HALON][PSTR]
    float* vs = sm + HALON * PSTR;

    const int b = blockIdx.z;
    const int ty0 = blockIdx.y * 8;
    const int tx0 = blockIdx.x * 8;
    const int tid = threadIdx.x;
    const float* wfold = g_wfold;

    // halo load: 144 positions x k,v 128 channels, reflect-padded, f4 coalesced
    for (int i = tid; i < HALON * 32; i += 256) {
        int hpos = i >> 5;
        int c4 = 16 + (i & 31);
        int hy = hpos / HALOW, hx = hpos % HALOW;
        int gy = refl(ty0 + hy - 2);
        int gx = refl(tx0 + hx - 2);
        float4 v = *(const float4*)(g_qkv +
            ((size_t)(b * HWSZ + gy * 56 + gx)) * 192 + c4 * 4);
        float* arr = (c4 < 32) ? ks : vs;
        *(float4*)(arr + hpos * PSTR + (c4 & 15) * 4) = v;
    }
    __syncthreads();

    const int pp = tid >> 3;            // pair 0..31
    const int s = tid & 7;              // channel sub / tap owner
    const int py = pp >> 2;             // 0..7
    const int px0 = (pp & 3) * 2;       // 0,2,4,6
    const int gy = ty0 + py, gx0 = tx0 + px0, gx1 = gx0 + 1;
    const int chidx = (py + 2) * HALOW + (px0 + 2);
    const int sb = s * 4;

    // q for both positions from gmem (L1-resident), packed pairs
    const float* qg0 = g_qkv + ((size_t)(b * HWSZ + gy * 56 + gx0)) * 192 + sb;
    ull qp0[4], qp1[4];
    float qr0[8], qr1[8];
    {
        float4 v0 = *(const float4*)(qg0);
        float4 v1 = *(const float4*)(qg0 + 32);
        qr0[0] = v0.x; qr0[1] = v0.y; qr0[2] = v0.z; qr0[3] = v0.w;
        qr0[4] = v1.x; qr0[5] = v1.y; qr0[6] = v1.z; qr0[7] = v1.w;
        qp0[0] = pk2(v0.x, v0.y); qp0[1] = pk2(v0.z, v0.w);
        qp0[2] = pk2(v1.x, v1.y); qp0[3] = pk2(v1.z, v1.w);
        float4 u0 = *(const float4*)(qg0 + 192);
        float4 u1 = *(const float4*)(qg0 + 224);
        qr1[0] = u0.x; qr1[1] = u0.y; qr1[2] = u0.z; qr1[3] = u0.w;
        qr1[4] = u1.x; qr1[5] = u1.y; qr1[6] = u1.z; qr1[7] = u1.w;
        qp1[0] = pk2(u0.x, u0.y); qp1[1] = pk2(u0.z, u0.w);
        qp1[2] = pk2(u1.x, u1.y); qp1[3] = pk2(u1.z, u1.w);
    }

    // packed conv accumulators (rate2 folded into weights)
    ull ocv0[4], ocv1[4];
#pragma unroll
    for (int c = 0; c < 4; ++c) { ocv0[c] = 0ull; ocv1[c] = 0ull; }

    // q-conv: 12 shared data loads serve 9+9 taps (zero padding via predicate)
#pragma unroll
    for (int dy = -1; dy <= 1; ++dy)
#pragma unroll
        for (int dx = -1; dx <= 2; ++dx) {
            if ((unsigned)(gy + dy) < 56u && (unsigned)(gx0 + dx) < 56u) {
                const float* qp = qg0 + (dy * 56 + dx) * 192;
                float4 q0 = *(const float4*)(qp);
                float4 q1 = *(const float4*)(qp + 32);
                ull qpk[4] = {pk2(q0.x, q0.y), pk2(q0.z, q0.w),
                              pk2(q1.x, q1.y), pk2(q1.z, q1.w)};
                if (dx <= 1) {
                    const float* wq = wfold + ((dy + 1) * 3 + dx + 1) * 64 + sb;
                    float4 w0 = __ldg((const float4*)(wq));
                    float4 w1 = __ldg((const float4*)(wq + 32));
                    fma2(ocv0[0], qpk[0], pk2(w0.x, w0.y));
                    fma2(ocv0[1], qpk[1], pk2(w0.z, w0.w));
                    fma2(ocv0[2], qpk[2], pk2(w1.x, w1.y));
                    fma2(ocv0[3], qpk[3], pk2(w1.z, w1.w));
                }
                if (dx >= 0) {
                    const float* wq = wfold + ((dy + 1) * 3 + dx) * 64 + sb;
                    float4 w0 = __ldg((const float4*)(wq));
                    float4 w1 = __ldg((const float4*)(wq + 32));
                    fma2(ocv1[0], qpk[0], pk2(w0.x, w0.y));
                    fma2(ocv1[1], qpk[1], pk2(w0.z, w0.w));
                    fma2(ocv1[2], qpk[2], pk2(w1.x, w1.y));
                    fma2(ocv1[3], qpk[3], pk2(w1.z, w1.w));
                }
            }
        }

    // phase 1: 30 k loads -> 50 packed dots (25 per position) + fused k-conv
    float attp0[4] = {0.f, 0.f, 0.f, 0.f};
    float attp1[4] = {0.f, 0.f, 0.f, 0.f};
#pragma unroll
    for (int dy = -2; dy <= 2; ++dy)
#pragma unroll
        for (int dx = -2; dx <= 3; ++dx) {
            const float* kb = ks + (chidx + dy * HALOW + dx) * PSTR + sb;
            float4 k0 = *(const float4*)(kb);
            float4 k1 = *(const float4*)(kb + 32);
            ull kpk[4] = {pk2(k0.x, k0.y), pk2(k0.z, k0.w),
                          pk2(k1.x, k1.y), pk2(k1.z, k1.w)};
            // fused k-conv (inner taps, zero padding)
            if (dy >= -1 && dy <= 1) {
                if ((unsigned)(gy + dy) < 56u && (unsigned)(gx0 + dx) < 56u) {
                    if (dx >= -1 && dx <= 1) {
                        const float* wk = wfold + 576 + ((dy + 1) * 3 + dx + 1) * 64 + sb;
                        float4 w0 = __ldg((const float4*)(wk));
                        float4 w1 = __ldg((const float4*)(wk + 32));
                        fma2(ocv0[0], kpk[0], pk2(w0.x, w0.y));
                        fma2(ocv0[1], kpk[1], pk2(w0.z, w0.w));
                        fma2(ocv0[2], kpk[2], pk2(w1.x, w1.y));
                        fma2(ocv0[3], kpk[3], pk2(w1.z, w1.w));
                    }
                    if (dx >= 0 && dx <= 2) {
                        const float* wk = wfold + 576 + ((dy + 1) * 3 + dx) * 64 + sb;
                        float4 w0 = __ldg((const float4*)(wk));
                        float4 w1 = __ldg((const float4*)(wk + 32));
                        fma2(ocv1[0], kpk[0], pk2(w0.x, w0.y));
                        fma2(ocv1[1], kpk[1], pk2(w0.z, w0.w));
                        fma2(ocv1[2], kpk[2], pk2(w1.x, w1.y));
                        fma2(ocv1[3], kpk[3], pk2(w1.z, w1.w));
                    }
                }
            }
            if (dx <= 2) {   // tap (dy,dx) of pos0, packed dot
                ull da = 0ull;
                fma2(da, qp0[0], kpk[0]);
                fma2(da, qp0[1], kpk[1]);
                fma2(da, qp0[2], kpk[2]);
                fma2(da, qp0[3], kpk[3]);
                float2 dd = up2(da);
                float d = seg8_add(dd.x + dd.y);
                const int j = (dy + 2) * 5 + dx + 2;
                if ((j & 7) == s) attp0[j >> 3] = d;
            }
            if (dx >= -1) {  // tap (dy,dx-1) of pos1, packed dot
                ull da = 0ull;
                fma2(da, qp1[0], kpk[0]);
                fma2(da, qp1[1], kpk[1]);
                fma2(da, qp1[2], kpk[2]);
                fma2(da, qp1[3], kpk[3]);
                float2 dd = up2(da);
                float d = seg8_add(dd.x + dd.y);
                const int j = (dy + 2) * 5 + dx + 1;
                if ((j & 7) == s) attp1[j >> 3] = d;
            }
        }

    // PE dots per position (bp cancels analytically)
    float a0 = 0.f, bq0 = 0.f, a1 = 0.f, bq1 = 0.f;
#pragma unroll
    for (int i = 0; i < 2; ++i)
#pragma unroll
        for (int j = 0; j < 4; ++j) {
            int ch = i * 32 + s * 4 + j;
            float2 w = __ldg((const float2*)wp + ch);
            a0 += qr0[i * 4 + j] * w.x; bq0 += qr0[i * 4 + j] * w.y;
            a1 += qr1[i * 4 + j] * w.x; bq1 += qr1[i * 4 + j] * w.y;
        }
    a0 = seg8_add(a0);
    bq0 = seg8_add(bq0);
    a1 = seg8_add(a1);
    bq1 = seg8_add(bq1);

    // phase 2: distributed softmax (lane s owns taps j%8==s), per position
    const float scaling = 0.125f;        // 64^-0.5
    const float lstep = 2.f / 55.f;
    const float r1 = rate1[0];
    const float r2 = rate2[0];

    float mx0 = -1e30f, mx1 = -1e30f;
#pragma unroll
    for (int i = 0; i < 4; ++i) {
        int j = s + 8 * i;
        if (j < 25) {
            int dy = j / 5 - 2, dx = j % 5 - 2;
            int gyj = refl(gy + dy);
            float t0 = scaling * (attp0[i] + a0 * ((float)(gx0 - refl(gx0 + dx)) * lstep) +
                                  bq0 * ((float)(gy - gyj) * lstep));
            float t1 = scaling * (attp1[i] + a1 * ((float)(gx1 - refl(gx1 + dx)) * lstep) +
                                  bq1 * ((float)(gy - gyj) * lstep));
            attp0[i] = t0; mx0 = fmaxf(mx0, t0);
            attp1[i] = t1; mx1 = fmaxf(mx1, t1);
        } else {
            attp0[i] = -1e30f;
            attp1[i] = -1e30f;
        }
    }
    mx0 = seg8_max(mx0);
    mx1 = seg8_max(mx1);
    float ss0 = 0.f, ss1 = 0.f;
#pragma unroll
    for (int i = 0; i < 4; ++i) {
        float e0 = __expf(attp0[i] - mx0); attp0[i] = e0; ss0 += e0;
        float e1 = __expf(attp1[i] - mx1); attp1[i] = e1; ss1 += e1;
    }
    ss0 = seg8_add(ss0);
    ss1 = seg8_add(ss1);
    const float c0n = r1 / ss0, c1n = r1 / ss1;
#pragma unroll
    for (int i = 0; i < 4; ++i) { attp0[i] *= c0n; attp1[i] *= c1n; }

    // phase 3: 30 v loads -> packed attention accumulate + fused v-conv
    ull oav0[4], oav1[4];
#pragma unroll
    for (int c = 0; c < 4; ++c) { oav0[c] = 0ull; oav1[c] = 0ull; }
#pragma unroll
    for (int dy = -2; dy <= 2; ++dy)
#pragma unroll
        for (int dx = -2; dx <= 3; ++dx) {
            const float* vb = vs + (chidx + dy * HALOW + dx) * PSTR + sb;
            float4 v0 = *(const float4*)(vb);
            float4 v1 = *(const float4*)(vb + 32);
            ull vpk[4] = {pk2(v0.x, v0.y), pk2(v0.z, v0.w),
                          pk2(v1.x, v1.y), pk2(v1.z, v1.w)};
            if (dx <= 2) {
                const int j = (dy + 2) * 5 + dx + 2;
                const float w = __shfl_sync(0xffffffffu, attp0[j >> 3], j & 7, 8);
                ull wb = bc2(w);
                fma2(oav0[0], vpk[0], wb);
                fma2(oav0[1], vpk[1], wb);
                fma2(oav0[2], vpk[2], wb);
                fma2(oav0[3], vpk[3], wb);
            }
            if (dx >= -1) {
                const int j = (dy + 2) * 5 + dx + 1;
                const float w = __shfl_sync(0xffffffffu, attp1[j >> 3], j & 7, 8);
                ull wb = bc2(w);
                fma2(oav1[0], vpk[0], wb);
                fma2(oav1[1], vpk[1], wb);
                fma2(oav1[2], vpk[2], wb);
                fma2(oav1[3], vpk[3], wb);
            }
            if (dy >= -1 && dy <= 1) {   // fused v-conv, zero padding
                if ((unsigned)(gy + dy) < 56u && (unsigned)(gx0 + dx) < 56u) {
                    if (dx >= -1 && dx <= 1) {
                        const float* wv = wfold + 1152 + ((dy + 1) * 3 + dx + 1) * 64 + sb;
                        float4 w0 = __ldg((const float4*)(wv));
                        float4 w1 = __ldg((const float4*)(wv + 32));
                        fma2(ocv0[0], vpk[0], pk2(w0.x, w0.y));
                        fma2(ocv0[1], vpk[1], pk2(w0.z, w0.w));
                        fma2(ocv0[2], vpk[2], pk2(w1.x, w1.y));
                        fma2(ocv0[3], vpk[3], pk2(w1.z, w1.w));
                    }
                    if (dx >= 0 && dx <= 2) {
                        const float* wv = wfold + 1152 + ((dy + 1) * 3 + dx) * 64 + sb;
                        float4 w0 = __ldg((const float4*)(wv));
                        float4 w1 = __ldg((const float4*)(wv + 32));
                        fma2(ocv1[0], vpk[0], pk2(w0.x, w0.y));
                        fma2(ocv1[1], vpk[1], pk2(w0.z, w0.w));
                        fma2(ocv1[2], vpk[2], pk2(w1.x, w1.y));
                        fma2(ocv1[3], vpk[3], pk2(w1.z, w1.w));
                    }
                }
            }
        }

#pragma unroll
    for (int c = 0; c < 4; ++c) {
        float2 av0 = up2(oav0[c]), av1 = up2(oav1[c]);
        float2 cv0 = up2(ocv0[c]), cv1 = up2(ocv1[c]);
        // pair c covers channels: i = c>>1, base = i*32 + s*4 + (c&1)*2
        int ch0 = (c >> 1) * 32 + s * 4 + (c & 1) * 2;
#pragma unroll
        for (int h = 0; h < 2; ++h) {
            int ch = ch0 + h;
            float bd = __ldg(b_dep + ch);
            float2 res;
            res.x = (h ? av0.y : av0.x) + (h ? cv0.y : cv0.x) + r2 * bd;
            res.y = (h ? av1.y : av1.x) + (h ? cv1.y : cv1.x) + r2 * bd;
            *(float2*)(out + ((size_t)(b * 64 + ch) * 56 + gy) * 56 + gx0) = res;
        }
    }
}

// ---------------- launch ----------------
extern "C" void kernel_launch(void* const* d_in, const int* in_sizes, int n_in,
                              void* d_out, int out_size) {
    const float* x    = (const float*)d_in[0];
    const float* w1   = (const float*)d_in[1];
    const float* b1   = (const float*)d_in[2];
    const float* w2   = (const float*)d_in[3];
    const float* b2   = (const float*)d_in[4];
    const float* w3   = (const float*)d_in[5];
    const float* b3   = (const float*)d_in[6];
    const float* wp   = (const float*)d_in[7];
    // d_in[8] = bp (cancels analytically)
    const float* w_fc = (const float*)d_in[9];
    const float* w_dep = (const float*)d_in[10];
    const float* b_dep = (const float*)d_in[11];
    const float* rate1 = (const float*)d_in[12];
    const float* rate2 = (const float*)d_in[13];
    float* out = (float*)d_out;

    const int qkv_smem = (64 * WS_STRIDE + 192) * 4;
    const int att_smem = 2 * HALON * PSTR * 4;   // 73728 B (k+v)
    cudaFuncSetAttribute(qkv_kernel, cudaFuncAttributeMaxDynamicSharedMemorySize, qkv_smem);
    cudaFuncSetAttribute(attn_kernel, cudaFuncAttributeMaxDynamicSharedMemorySize, att_smem);

    qkv_kernel<<<dim3(49, 8), 256, qkv_smem>>>(x, w1, b1, w2, b2, w3, b3, w_fc, w_dep, rate2);
    attn_kernel<<<dim3(7, 7, 8), 256, att_smem>>>(wp, b_dep, rate1, rate2, out);
}